// round 1
// baseline (speedup 1.0000x reference)
#include <cuda_runtime.h>
#include <math.h>

#define T_DIM 512
#define B_DIM 32
#define V_DIM 4096
#define S_DIM 64
#define L_DIM 129              // 2*S + 1
#define LPW   65               // stored log-probs per (b,t): blank + 64 labels

#define LOG2E 1.4426950408889634f
#define LN2   0.6931471805599453f
#define NEG2  (-1.4426950408889634e30f)   // -1e30 * log2(e)

// Scratch: per-(b,t) gathered log2-probs, and per-batch NLL.
__device__ float g_lp[(size_t)B_DIM * T_DIM * LPW];
__device__ float g_nll[B_DIM];

// ---------------------------------------------------------------------------
// Kernel 1: per (t,b) row of acts (4096 f32): logsumexp + gather 65 classes.
// One block per row, 256 threads, 16 floats/thread via float4 (fully coalesced).
// Writes lp2[j] = (x[cls_j] - max)*log2e - log2(sum exp(x - max))  into (B,T,65).
// ---------------------------------------------------------------------------
__global__ __launch_bounds__(256) void k_lse_gather(
    const float* __restrict__ acts, const int* __restrict__ labels) {
    const int row = blockIdx.x;            // t*B + b
    const int t   = row / B_DIM;
    const int b   = row - t * B_DIM;
    const float* __restrict__ x = acts + (size_t)row * V_DIM;
    const int tid = threadIdx.x;

    const float4* __restrict__ x4 = reinterpret_cast<const float4*>(x);
    float4 r0 = x4[tid];
    float4 r1 = x4[tid + 256];
    float4 r2 = x4[tid + 512];
    float4 r3 = x4[tid + 768];

    float m = fmaxf(fmaxf(fmaxf(r0.x, r0.y), fmaxf(r0.z, r0.w)),
                    fmaxf(fmaxf(r1.x, r1.y), fmaxf(r1.z, r1.w)));
    m = fmaxf(m, fmaxf(fmaxf(fmaxf(r2.x, r2.y), fmaxf(r2.z, r2.w)),
                       fmaxf(fmaxf(r3.x, r3.y), fmaxf(r3.z, r3.w))));

    __shared__ float s_m[8];
    __shared__ float s_s[8];
    __shared__ float s_bcast[2];

    #pragma unroll
    for (int o = 16; o; o >>= 1) m = fmaxf(m, __shfl_xor_sync(0xffffffffu, m, o));
    if ((tid & 31) == 0) s_m[tid >> 5] = m;
    __syncthreads();
    if (tid < 32) {
        float v = (tid < 8) ? s_m[tid] : -3.4e38f;
        #pragma unroll
        for (int o = 4; o; o >>= 1) v = fmaxf(v, __shfl_xor_sync(0xffffffffu, v, o));
        if (tid == 0) s_bcast[0] = v;
    }
    __syncthreads();
    const float vmax = s_bcast[0];

    float s = 0.0f;
    s += exp2f((r0.x - vmax) * LOG2E) + exp2f((r0.y - vmax) * LOG2E)
       + exp2f((r0.z - vmax) * LOG2E) + exp2f((r0.w - vmax) * LOG2E);
    s += exp2f((r1.x - vmax) * LOG2E) + exp2f((r1.y - vmax) * LOG2E)
       + exp2f((r1.z - vmax) * LOG2E) + exp2f((r1.w - vmax) * LOG2E);
    s += exp2f((r2.x - vmax) * LOG2E) + exp2f((r2.y - vmax) * LOG2E)
       + exp2f((r2.z - vmax) * LOG2E) + exp2f((r2.w - vmax) * LOG2E);
    s += exp2f((r3.x - vmax) * LOG2E) + exp2f((r3.y - vmax) * LOG2E)
       + exp2f((r3.z - vmax) * LOG2E) + exp2f((r3.w - vmax) * LOG2E);

    #pragma unroll
    for (int o = 16; o; o >>= 1) s += __shfl_xor_sync(0xffffffffu, s, o);
    if ((tid & 31) == 0) s_s[tid >> 5] = s;
    __syncthreads();
    if (tid < 32) {
        float v = (tid < 8) ? s_s[tid] : 0.0f;
        #pragma unroll
        for (int o = 4; o; o >>= 1) v += __shfl_xor_sync(0xffffffffu, v, o);
        if (tid == 0) s_bcast[1] = __log2f(v);
    }
    __syncthreads();
    const float log2sum = s_bcast[1];

    if (tid < LPW) {
        const int cls = (tid == 0) ? 0 : labels[b * S_DIM + tid - 1];
        const float v = x[cls];                 // L1/L2 hit (row just read)
        g_lp[((size_t)b * T_DIM + t) * LPW + tid] = (v - vmax) * LOG2E - log2sum;
    }
}

// ---------------------------------------------------------------------------
// Kernel 2: CTC alpha recursion, one block per batch element.
// The whole (T,65) lp slab for this batch (133 KB) is preloaded into dynamic
// smem; alpha double-buffered in static smem; one barrier per timestep.
// All math in log2 domain (native EX2/LG2).
// ---------------------------------------------------------------------------
__global__ __launch_bounds__(160) void k_alpha(
    const int* __restrict__ labels,
    const int* __restrict__ input_len,
    const int* __restrict__ target_len) {
    extern __shared__ float slp[];                 // T_DIM * LPW floats
    __shared__ float A[2][L_DIM + 3];              // index s+2; [0..1] = NEG pad

    const int b   = blockIdx.x;
    const int tid = threadIdx.x;

    // Preload lp slab (contiguous, float4): 8320 float4 / 160 thr = 52 each.
    {
        const float4* __restrict__ src =
            reinterpret_cast<const float4*>(g_lp + (size_t)b * T_DIM * LPW);
        float4* dst = reinterpret_cast<float4*>(slp);
        const int n4 = (T_DIM * LPW) / 4;
        for (int i = tid; i < n4; i += 160) dst[i] = src[i];
    }

    const int  s      = tid;
    const bool active = (s < L_DIM);
    int  j = 0;
    bool doskip = false;
    if (active && (s & 1)) {
        const int k = (s - 1) >> 1;                // 0-based label index
        j = k + 1;
        if (s >= 3) doskip = (labels[b * S_DIM + k] != labels[b * S_DIM + k - 1]);
    }

    if (tid < L_DIM + 3) { A[0][tid] = NEG2; A[1][tid] = NEG2; }
    __syncthreads();
    if (tid == 0) { A[0][2] = slp[0]; A[0][3] = slp[1]; }
    __syncthreads();

    const int len = input_len[b];
    int p = 0;
    int off = LPW;
    for (int t = 1; t < T_DIM; ++t) {
        if (active) {
            const float a  = A[p][s + 2];
            const float a1 = A[p][s + 1];
            const float a2 = doskip ? A[p][s] : NEG2;
            const float m  = fmaxf(a, fmaxf(a1, a2));
            const float sum = exp2f(a - m) + exp2f(a1 - m) + exp2f(a2 - m);
            const float nv  = m + __log2f(sum) + slp[off + j];
            A[p ^ 1][s + 2] = (t < len) ? nv : a;
        }
        __syncthreads();
        p ^= 1;
        off += LPW;
    }

    if (tid == 0) {
        int hi = 2 * target_len[b];
        if (hi > L_DIM - 1) hi = L_DIM - 1;
        int lo = hi - 1; if (lo < 0) lo = 0;
        const float ah = A[p][hi + 2];
        const float al = A[p][lo + 2];
        const float m  = fmaxf(ah, al);
        float v = -(m + __log2f(exp2f(ah - m) + exp2f(al - m))) * LN2;
        if (!isfinite(v) || v > 1e29f) v = 0.0f;
        g_nll[b] = v;
    }
}

// ---------------------------------------------------------------------------
// Kernel 3: sum 32 NLLs -> scalar output.
// ---------------------------------------------------------------------------
__global__ void k_sum(float* __restrict__ out) {
    float v = g_nll[threadIdx.x];
    #pragma unroll
    for (int o = 16; o; o >>= 1) v += __shfl_xor_sync(0xffffffffu, v, o);
    if (threadIdx.x == 0) out[0] = v;
}

extern "C" void kernel_launch(void* const* d_in, const int* in_sizes, int n_in,
                              void* d_out, int out_size) {
    const float* acts   = (const float*)d_in[0];
    const int*   labels = (const int*)d_in[1];
    const int*   ilen   = (const int*)d_in[2];
    const int*   tlen   = (const int*)d_in[3];
    (void)in_sizes; (void)n_in; (void)out_size;

    const int smem_bytes = T_DIM * LPW * (int)sizeof(float);   // 133120
    cudaFuncSetAttribute(k_alpha, cudaFuncAttributeMaxDynamicSharedMemorySize,
                         smem_bytes);

    k_lse_gather<<<T_DIM * B_DIM, 256>>>(acts, labels);
    k_alpha<<<B_DIM, 160, smem_bytes>>>(labels, ilen, tlen);
    k_sum<<<1, 32>>>((float*)d_out);
}

// round 2
// speedup vs baseline: 1.5386x; 1.5386x over previous
#include <cuda_runtime.h>
#include <math.h>

#define T_DIM 512
#define B_DIM 32
#define V_DIM 4096
#define S_DIM 64
#define L_DIM 129              // 2*S + 1
#define LPW   65               // stored probs per (b,t): blank + 64 labels

#define LOG2E 1.4426950408889634f
#define LN2   0.6931471805599453f

// Scratch: per-(b,t) gathered LINEAR softmax probs, and per-batch NLL.
__device__ float g_p[(size_t)B_DIM * T_DIM * LPW];
__device__ float g_nll[B_DIM];

__device__ __forceinline__ float ex2(float x) {
    float y; asm("ex2.approx.f32 %0, %1;" : "=f"(y) : "f"(x)); return y;
}
__device__ __forceinline__ float lg2(float x) {
    float y; asm("lg2.approx.f32 %0, %1;" : "=f"(y) : "f"(x)); return y;
}

// ---------------------------------------------------------------------------
// Kernel 1: per (t,b) row of acts (4096 f32): one-pass sum(exp), then gather
// 65 classes as LINEAR probs p = exp(x - logsumexp). (B,T,65) layout.
// ---------------------------------------------------------------------------
__global__ __launch_bounds__(256) void k_lse_gather(
    const float* __restrict__ acts, const int* __restrict__ labels) {
    const int row = blockIdx.x;            // t*B + b
    const int t   = row / B_DIM;
    const int b   = row - t * B_DIM;
    const float* __restrict__ x = acts + (size_t)row * V_DIM;
    const int tid = threadIdx.x;

    const float4* __restrict__ x4 = reinterpret_cast<const float4*>(x);
    float s = 0.0f;
    #pragma unroll
    for (int k = 0; k < 4; ++k) {
        float4 r = x4[tid + 256 * k];
        s += ex2(r.x * LOG2E) + ex2(r.y * LOG2E)
           + ex2(r.z * LOG2E) + ex2(r.w * LOG2E);
    }

    __shared__ float s_s[8];
    __shared__ float s_bcast;
    #pragma unroll
    for (int o = 16; o; o >>= 1) s += __shfl_xor_sync(0xffffffffu, s, o);
    if ((tid & 31) == 0) s_s[tid >> 5] = s;
    __syncthreads();
    if (tid < 32) {
        float v = (tid < 8) ? s_s[tid] : 0.0f;
        #pragma unroll
        for (int o = 4; o; o >>= 1) v += __shfl_xor_sync(0xffffffffu, v, o);
        if (tid == 0) s_bcast = lg2(v);
    }
    __syncthreads();
    const float log2sum = s_bcast;

    if (tid < LPW) {
        const int cls = (tid == 0) ? 0 : labels[b * S_DIM + tid - 1];
        g_p[((size_t)b * T_DIM + t) * LPW + tid] =
            ex2(x[cls] * LOG2E - log2sum);
    }
}

// ---------------------------------------------------------------------------
// Kernel 2: scaled LINEAR-domain CTC alpha recursion. One warp per batch.
// alpha held in registers (4 slots/thread, blocked; lane31 owns s=128 extra).
// Only ONE shfl_up per step; probs preloaded to smem; exact pow2 renorm
// every 4 steps via exponent bit tricks (no MUFU in the loop).
// ---------------------------------------------------------------------------
__global__ __launch_bounds__(32) void k_alpha(
    const int* __restrict__ labels,
    const int* __restrict__ input_len,
    const int* __restrict__ target_len) {
    extern __shared__ float sp[];                 // T_DIM * LPW floats
    const int b    = blockIdx.x;
    const int lane = threadIdx.x;

    // Preload prob slab (contiguous float4): 8320 f4 / 32 lanes = 260 each.
    {
        const float4* __restrict__ src =
            reinterpret_cast<const float4*>(g_p + (size_t)b * T_DIM * LPW);
        float4* dst = reinterpret_cast<float4*>(sp);
        for (int i = lane; i < (T_DIM * LPW) / 4; i += 32) dst[i] = src[i];
    }

    // Per-thread static info. Thread `lane` owns s = 4*lane + {0,1,2,3};
    // lane 31 additionally owns s = 128.
    // Odd slots: s=4i+1 -> label idx 2i, prob j=2i+1 ; s=4i+3 -> label 2i+1, j=2i+2.
    const int j1 = 2 * lane + 1;
    const int j2 = 2 * lane + 2;
    const int* lab = labels + b * S_DIM;
    const bool sk1 = (lane >= 1) && (lab[2 * lane] != lab[2 * lane - 1]);
    const bool sk3 = (lab[2 * lane + 1] != lab[2 * lane]);
    const bool last = (lane == 31);

    __syncwarp();

    // Init at t=0: alpha[0]=p[0][0], alpha[1]=p[0][1], rest 0.
    float a0 = (lane == 0) ? sp[0] : 0.0f;
    float a1 = (lane == 0) ? sp[1] : 0.0f;
    float a2 = 0.0f, a3 = 0.0f, a4 = 0.0f;
    int   E  = 0;                                  // accumulated exponent

    const int len = input_len[b];

    // Prefetch probs for t=1.
    float pb  = sp[LPW + 0];
    float pl1 = sp[LPW + j1];
    float pl2 = sp[LPW + j2];

    for (int t = 1; t < len; ++t) {
        // Prefetch next step's probs (clamped index; hides LDS latency).
        const int tn  = (t + 1 < T_DIM) ? t + 1 : t;
        const int off = tn * LPW;
        const float npb  = sp[off];
        const float npl1 = sp[off + j1];
        const float npl2 = sp[off + j2];

        // Neighbor value: previous thread's slot3 (old).
        float p3 = __shfl_up_sync(0xffffffffu, a3, 1);
        if (lane == 0) p3 = 0.0f;

        const float n0 = (a0 + p3) * pb;
        const float n1 = (a1 + a0 + (sk1 ? p3 : 0.0f)) * pl1;
        const float n2 = (a2 + a1) * pb;
        const float n3 = (a3 + a2 + (sk3 ? a1 : 0.0f)) * pl2;
        const float n4 = (a4 + a3) * pb;           // only meaningful on lane 31

        a0 = n0; a1 = n1; a2 = n2; a3 = n3;
        if (last) a4 = n4;

        pb = npb; pl1 = npl1; pl2 = npl2;

        if ((t & 3) == 0) {
            float m = fmaxf(fmaxf(a0, a1), fmaxf(a2, a3));
            if (last) m = fmaxf(m, a4);
            #pragma unroll
            for (int o = 16; o; o >>= 1)
                m = fmaxf(m, __shfl_xor_sync(0xffffffffu, m, o));
            if (m > 0.0f) {
                const unsigned u = __float_as_uint(m);
                const int e = (int)((u >> 23) & 255u);
                E += e - 127;
                const float sc = __uint_as_float((unsigned)(254 - e) << 23);
                a0 *= sc; a1 *= sc; a2 *= sc; a3 *= sc; a4 *= sc;
            }
        }
    }

    // Stash alphas (reuse smem) and let lane 0 finish.
    sp[4 * lane + 0] = a0;
    sp[4 * lane + 1] = a1;
    sp[4 * lane + 2] = a2;
    sp[4 * lane + 3] = a3;
    if (last) sp[128] = a4;
    __syncwarp();

    if (lane == 0) {
        int hi = 2 * target_len[b];
        if (hi > L_DIM - 1) hi = L_DIM - 1;
        int lo = hi - 1; if (lo < 0) lo = 0;
        const float sum = sp[hi] + sp[lo];
        float v = -(lg2(sum) + (float)E) * LN2;
        if (!isfinite(v) || v > 1e29f || sum <= 0.0f) v = 0.0f;
        g_nll[b] = v;
    }
}

// ---------------------------------------------------------------------------
// Kernel 3: sum 32 NLLs -> scalar output.
// ---------------------------------------------------------------------------
__global__ void k_sum(float* __restrict__ out) {
    float v = g_nll[threadIdx.x];
    #pragma unroll
    for (int o = 16; o; o >>= 1) v += __shfl_xor_sync(0xffffffffu, v, o);
    if (threadIdx.x == 0) out[0] = v;
}

extern "C" void kernel_launch(void* const* d_in, const int* in_sizes, int n_in,
                              void* d_out, int out_size) {
    const float* acts   = (const float*)d_in[0];
    const int*   labels = (const int*)d_in[1];
    const int*   ilen   = (const int*)d_in[2];
    const int*   tlen   = (const int*)d_in[3];
    (void)in_sizes; (void)n_in; (void)out_size;

    const int smem_bytes = T_DIM * LPW * (int)sizeof(float);   // 133120
    cudaFuncSetAttribute(k_alpha, cudaFuncAttributeMaxDynamicSharedMemorySize,
                         smem_bytes);

    k_lse_gather<<<T_DIM * B_DIM, 256>>>(acts, labels);
    k_alpha<<<B_DIM, 32, smem_bytes>>>(labels, ilen, tlen);
    k_sum<<<1, 32>>>((float*)d_out);
}

// round 3
// speedup vs baseline: 2.1230x; 1.3798x over previous
#include <cuda_runtime.h>
#include <math.h>

#define T_DIM 512
#define B_DIM 32
#define V_DIM 4096
#define S_DIM 64
#define L_DIM 129              // 2*S + 1
#define LPW   65               // stored probs per (b,t): blank + 64 labels

#define LOG2E 1.4426950408889634f
#define LN2   0.6931471805599453f

// Scratch: per-(b,t) gathered LINEAR softmax probs, and per-batch NLL.
__device__ float g_p[(size_t)B_DIM * T_DIM * LPW];
__device__ float g_nll[B_DIM];

__device__ __forceinline__ float ex2(float x) {
    float y; asm("ex2.approx.f32 %0, %1;" : "=f"(y) : "f"(x)); return y;
}
__device__ __forceinline__ float lg2(float x) {
    float y; asm("lg2.approx.f32 %0, %1;" : "=f"(y) : "f"(x)); return y;
}
__device__ __forceinline__ unsigned warp_max_u32(unsigned v) {
    unsigned r;
    asm("redux.sync.max.u32 %0, %1, 0xffffffff;" : "=r"(r) : "r"(v));
    return r;
}

// ---------------------------------------------------------------------------
// Kernel 1: per (t,b) row of acts (4096 f32): one-pass sum(exp), then gather
// 65 classes as LINEAR probs p = exp(x - logsumexp). (B,T,65) layout.
// ---------------------------------------------------------------------------
__global__ __launch_bounds__(256) void k_lse_gather(
    const float* __restrict__ acts, const int* __restrict__ labels) {
    const int row = blockIdx.x;            // t*B + b
    const int t   = row / B_DIM;
    const int b   = row - t * B_DIM;
    const float* __restrict__ x = acts + (size_t)row * V_DIM;
    const int tid = threadIdx.x;

    const float4* __restrict__ x4 = reinterpret_cast<const float4*>(x);
    float s = 0.0f;
    #pragma unroll
    for (int k = 0; k < 4; ++k) {
        float4 r = __ldcs(&x4[tid + 256 * k]);   // stream, evict-first
        s += ex2(r.x * LOG2E) + ex2(r.y * LOG2E)
           + ex2(r.z * LOG2E) + ex2(r.w * LOG2E);
    }

    __shared__ float s_s[8];
    __shared__ float s_bcast;
    #pragma unroll
    for (int o = 16; o; o >>= 1) s += __shfl_xor_sync(0xffffffffu, s, o);
    if ((tid & 31) == 0) s_s[tid >> 5] = s;
    __syncthreads();
    if (tid < 32) {
        float v = (tid < 8) ? s_s[tid] : 0.0f;
        #pragma unroll
        for (int o = 4; o; o >>= 1) v += __shfl_xor_sync(0xffffffffu, v, o);
        if (tid == 0) s_bcast = lg2(v);
    }
    __syncthreads();
    const float log2sum = s_bcast;

    if (tid < LPW) {
        const int cls = (tid == 0) ? 0 : __ldg(&labels[b * S_DIM + tid - 1]);
        g_p[((size_t)b * T_DIM + t) * LPW + tid] =
            ex2(x[cls] * LOG2E - log2sum);
    }
}

// ---------------------------------------------------------------------------
// Kernel 2: scaled LINEAR-domain CTC alpha recursion. One warp per batch.
// alpha in registers (4 slots/thread blocked + s=128 on lane31). One shfl_up
// per step. Time loop unrolled x4; renorm once per block via redux.sync
// (single-instruction warp max on float bits). No branches in the hot path.
// ---------------------------------------------------------------------------
__global__ __launch_bounds__(32) void k_alpha(
    const int* __restrict__ labels,
    const int* __restrict__ input_len,
    const int* __restrict__ target_len) {
    extern __shared__ float sp[];                 // T_DIM * LPW floats
    const int b    = blockIdx.x;
    const int lane = threadIdx.x;

    // Preload prob slab (contiguous float4): 8320 f4 / 32 lanes = 260 each.
    {
        const float4* __restrict__ src =
            reinterpret_cast<const float4*>(g_p + (size_t)b * T_DIM * LPW);
        float4* dst = reinterpret_cast<float4*>(sp);
        #pragma unroll 4
        for (int i = lane; i < (T_DIM * LPW) / 4; i += 32) dst[i] = src[i];
    }

    // Thread `lane` owns s = 4*lane + {0,1,2,3}; lane 31 also owns s = 128.
    const int j1 = 2 * lane + 1;
    const int j2 = 2 * lane + 2;
    const int* lab = labels + b * S_DIM;
    const bool sk1 = (lane >= 1) && (lab[2 * lane] != lab[2 * lane - 1]);
    const bool sk3 = (lab[2 * lane + 1] != lab[2 * lane]);

    __syncwarp();

    float a0 = (lane == 0) ? sp[0] : 0.0f;
    float a1 = (lane == 0) ? sp[1] : 0.0f;
    float a2 = 0.0f, a3 = 0.0f, a4 = 0.0f;
    int   E  = 0;

    const int len = input_len[b];

    auto step = [&](float pb, float pl1, float pl2) {
        float p3 = __shfl_up_sync(0xffffffffu, a3, 1);
        p3 = (lane == 0) ? 0.0f : p3;
        const float n0 = (a0 + p3) * pb;
        const float n1 = (a1 + a0 + (sk1 ? p3 : 0.0f)) * pl1;
        const float n2 = (a2 + a1) * pb;
        const float n3 = (a3 + a2 + (sk3 ? a1 : 0.0f)) * pl2;
        a4 = (a4 + a3) * pb;      // real only on lane31; junk elsewhere (benign)
        a0 = n0; a1 = n1; a2 = n2; a3 = n3;
    };

    int t = 1;
    const int nfull = (len - 1) >> 2;
    #pragma unroll 1
    for (int blk = 0; blk < nfull; ++blk) {
        const int off = t * LPW;
        // 12 independent LDS prefetches for the 4 steps.
        const float pb0 = sp[off + 0 * LPW], q0 = sp[off + 0 * LPW + j1], r0 = sp[off + 0 * LPW + j2];
        const float pb1 = sp[off + 1 * LPW], q1 = sp[off + 1 * LPW + j1], r1 = sp[off + 1 * LPW + j2];
        const float pb2 = sp[off + 2 * LPW], q2 = sp[off + 2 * LPW + j1], r2 = sp[off + 2 * LPW + j2];
        const float pb3 = sp[off + 3 * LPW], q3 = sp[off + 3 * LPW + j1], r3 = sp[off + 3 * LPW + j2];

        step(pb0, q0, r0);
        step(pb1, q1, r1);
        step(pb2, q2, r2);
        step(pb3, q3, r3);

        // Renorm: single-instruction warp max on float bit patterns.
        float m = fmaxf(fmaxf(a0, a1), fmaxf(fmaxf(a2, a3), a4));
        const unsigned g = warp_max_u32(__float_as_uint(m));
        if (g) {
            const int e = (int)(g >> 23);
            E += e - 127;
            const float sc = __uint_as_float((unsigned)(254 - e) << 23);
            a0 *= sc; a1 *= sc; a2 *= sc; a3 *= sc; a4 *= sc;
        }
        t += 4;
    }
    #pragma unroll 1
    for (; t < len; ++t) {
        const int off = t * LPW;
        step(sp[off], sp[off + j1], sp[off + j2]);
    }

    // Stash alphas (reuse smem) and let lane 0 finish.
    sp[4 * lane + 0] = a0;
    sp[4 * lane + 1] = a1;
    sp[4 * lane + 2] = a2;
    sp[4 * lane + 3] = a3;
    if (lane == 31) sp[128] = a4;
    __syncwarp();

    if (lane == 0) {
        int hi = 2 * target_len[b];
        if (hi > L_DIM - 1) hi = L_DIM - 1;
        int lo = hi - 1; if (lo < 0) lo = 0;
        const float sum = sp[hi] + sp[lo];
        float v = -(lg2(sum) + (float)E) * LN2;
        if (!isfinite(v) || v > 1e29f || sum <= 0.0f) v = 0.0f;
        g_nll[b] = v;
    }
}

// ---------------------------------------------------------------------------
// Kernel 3: sum 32 NLLs -> scalar output.
// ---------------------------------------------------------------------------
__global__ void k_sum(float* __restrict__ out) {
    float v = g_nll[threadIdx.x];
    #pragma unroll
    for (int o = 16; o; o >>= 1) v += __shfl_xor_sync(0xffffffffu, v, o);
    if (threadIdx.x == 0) out[0] = v;
}

extern "C" void kernel_launch(void* const* d_in, const int* in_sizes, int n_in,
                              void* d_out, int out_size) {
    const float* acts   = (const float*)d_in[0];
    const int*   labels = (const int*)d_in[1];
    const int*   ilen   = (const int*)d_in[2];
    const int*   tlen   = (const int*)d_in[3];
    (void)in_sizes; (void)n_in; (void)out_size;

    const int smem_bytes = T_DIM * LPW * (int)sizeof(float);   // 133120
    cudaFuncSetAttribute(k_alpha, cudaFuncAttributeMaxDynamicSharedMemorySize,
                         smem_bytes);

    k_lse_gather<<<T_DIM * B_DIM, 256>>>(acts, labels);
    k_alpha<<<B_DIM, 32, smem_bytes>>>(labels, ilen, tlen);
    k_sum<<<1, 32>>>((float*)d_out);
}